// round 12
// baseline (speedup 1.0000x reference)
#include <cuda_runtime.h>

#define NN   4096
#define TT   300
#define TW   10
#define NBLK 128
#define NT1  256
#define NT2  512
#define CW    48                 // cached slot words (rows 0..1535)
#define CROWS (CW * 32)          // 1536
#define CSTR  33                 // cache row stride in floats (conflict-free)

// smem layout offsets (bytes)
#define OFF_CACHE  0
#define OFF_PART4  (CROWS * CSTR * 4)            // 202752
#define OFF_PARTC  (OFF_PART4 + 16 * 9 * 16)     // +2304
#define OFF_IDXC   (OFF_PARTC + 16 * 33 * 4)     // +2112
#define OFF_IDXU   (OFF_IDXC + 1664 * 2)         // +3328
#define OFF_MASK   (OFF_IDXU + 2688 * 2)         // +5376
#define OFF_OFFS   (OFF_MASK + 128 * 4)
#define OFF_TOT    (OFF_OFFS + 128 * 4)
#define SMEM_SZ    (OFF_TOT + 16)

// ---------------- device scratch ----------------
__device__ unsigned g_mask[NN * TW];
__device__ float    g_Xpart[4ull * 320 * NN];
__device__ __align__(256) unsigned long long g_slot[TT][NBLK];  // {tag=t+1, mask}
__device__ unsigned g_flag[TT];                                  // aggregator flag

__device__ __forceinline__ void ldcgv2(const unsigned long long* p,
                                       unsigned long long& a, unsigned long long& b) {
    asm volatile("ld.global.cg.v2.u64 {%0,%1}, [%2];" : "=l"(a), "=l"(b) : "l"(p));
}
__device__ __forceinline__ void stcg64(unsigned long long* p, unsigned long long v) {
    asm volatile("st.global.cg.b64 [%0], %1;" :: "l"(p), "l"(v));
}
__device__ __forceinline__ unsigned ldcg32(const unsigned* p) {
    unsigned v; asm volatile("ld.global.cg.b32 %0, [%1];" : "=r"(v) : "l"(p)); return v;
}
__device__ __forceinline__ void stcg32(unsigned* p, unsigned v) {
    asm volatile("st.global.cg.b32 [%0], %1;" :: "l"(p), "r"(v));
}
__device__ __forceinline__ float4 ldcg128(const float* p) {
    float4 v;
    asm volatile("ld.global.cg.v4.f32 {%0,%1,%2,%3}, [%4];"
                 : "=f"(v.x), "=f"(v.y), "=f"(v.z), "=f"(v.w) : "l"(p));
    return v;
}

// ---------------- kernel 1: pack inp bits + clear sync state ----------------
__global__ void __launch_bounds__(256) pack_kernel(const int* __restrict__ inp) {
    const int blk  = blockIdx.x;
    const int word = blk % TW;
    const int i    = (blk / TW) * 256 + threadIdx.x;
    unsigned m = 0u;
    const int tb = word * 32;
    #pragma unroll
    for (int b = 0; b < 32; ++b) {
        int t = tb + b;
        if (t < TT) m |= (((unsigned)inp[(size_t)t * NN + i]) & 1u) << b;
    }
    g_mask[i * TW + word] = m;
    int gid = blk * 256 + threadIdx.x;
    if (gid < TT * NBLK) ((unsigned long long*)g_slot)[gid] = 0ull;
    if (gid < TT) g_flag[gid] = 0u;
}

// ---------------- kernel 2: X partials via packed f32x2 FFMA (exact) ----------
__global__ void __launch_bounds__(NT1) xgemm_kernel(const float* __restrict__ w) {
    __shared__ unsigned long long Adup[128][18];
    const int tid  = threadIdx.x;
    const int tile = blockIdx.x;
    int word = tile % 10;
    int ccq  = tile / 10;
    int cc   = ccq >> 2;
    int q    = ccq & 3;
    int j    = cc * 256 + tid;
    int ibase = q * 1024;

    unsigned long long acc[16];
    #pragma unroll
    for (int k = 0; k < 16; ++k) acc[k] = 0ull;

    for (int sub = 0; sub < 8; ++sub) {
        int ib = ibase + sub * 128;
        __syncthreads();
        for (int e = tid; e < 2048; e += NT1) {
            int ii = e >> 4, tp = e & 15;
            unsigned m  = g_mask[(ib + ii) * TW + word];
            unsigned lo = (m >> (2 * tp))     & 1u ? 0x3f800000u : 0u;
            unsigned hi = (m >> (2 * tp + 1)) & 1u ? 0x3f800000u : 0u;
            Adup[ii][tp] = ((unsigned long long)hi << 32) | lo;
        }
        __syncthreads();
        for (int ii = 0; ii < 128; ++ii) {
            unsigned wu = __float_as_uint(w[(size_t)(ib + ii) * NN + j]);
            unsigned long long wpk;
            asm("mov.b64 %0, {%1, %1};" : "=l"(wpk) : "r"(wu));
            const ulonglong2* ap = (const ulonglong2*)(&Adup[ii][0]);
            #pragma unroll
            for (int k = 0; k < 8; ++k) {
                ulonglong2 a2 = ap[k];
                asm("fma.rn.f32x2 %0, %1, %2, %0;" : "+l"(acc[2*k])   : "l"(wpk), "l"(a2.x));
                asm("fma.rn.f32x2 %0, %1, %2, %0;" : "+l"(acc[2*k+1]) : "l"(wpk), "l"(a2.y));
            }
        }
    }
    #pragma unroll
    for (int tp = 0; tp < 16; ++tp) {
        int t0 = word * 32 + 2 * tp;
        g_Xpart[((size_t)q * 320 + t0)     * NN + j] = __uint_as_float((unsigned)acc[tp]);
        g_Xpart[((size_t)q * 320 + t0 + 1) * NN + j] = __uint_as_float((unsigned)(acc[tp] >> 32));
    }
}

// ---------------- kernel 3: persistent recurrent LIF ---------------------------
// Blocks 0..127: workers. Block 128: aggregator (sole poller of g_slot).
// Workers cache w_rec rows 0..1535 (their 32 columns) in conflict-free smem.
__global__ void __launch_bounds__(NT2, 1)
lif_kernel(const float* __restrict__ w_rec, float* __restrict__ out) {
    extern __shared__ char sm[];
    float*          cache  = (float*)(sm + OFF_CACHE);           // [1536][33]
    float4        (*part4)[9]  = (float4(*)[9])(sm + OFF_PART4); // L2-path partials
    float         (*part_c)[33] = (float(*)[33])(sm + OFF_PARTC);// smem-path partials
    unsigned short* idxC   = (unsigned short*)(sm + OFF_IDXC);
    unsigned short* idxU   = (unsigned short*)(sm + OFF_IDXU);
    unsigned*       sh_mask = (unsigned*)(sm + OFF_MASK);
    int*            sh_off  = (int*)(sm + OFF_OFFS);
    int*            sh_tot  = (int*)(sm + OFF_TOT);              // [0]=C, [1]=U

    const int tid = threadIdx.x;
    const int bid = blockIdx.x;
    const int l   = tid & 31;
    const int wp  = tid >> 5;

    // ================= aggregator block =================
    if (bid == NBLK) {
        if (wp != 0) return;
        for (int t = 0; t < TT - 1; ++t) {
            const unsigned long long* slot = &g_slot[t][4 * l];
            const unsigned want = (unsigned)(t + 1);
            unsigned long long a0, a1, b0, b1;
            bool okA = false, okB = false;
            while (1) {
                if (!okA) {
                    ldcgv2(slot, a0, a1);
                    okA = ((unsigned)(a0 >> 32) == want) & ((unsigned)(a1 >> 32) == want);
                }
                if (!okB) {
                    ldcgv2(slot + 2, b0, b1);
                    okB = ((unsigned)(b0 >> 32) == want) & ((unsigned)(b1 >> 32) == want);
                }
                if (__all_sync(0xffffffffu, okA & okB)) break;
            }
            if (l == 0) stcg32(&g_flag[t], want);   // workers tag-check slots anyway
        }
        return;
    }

    // ================= worker blocks =================
    const int sub = l >> 3;
    const int ln8 = l & 7;
    const int j0  = bid * 32;

    // preload smem weight cache: rows 0..CROWS-1, this block's 32 columns
    for (int q = tid; q < CROWS * 32; q += NT2) {
        int row = q >> 5, c = q & 31;
        cache[row * CSTR + c] = w_rec[(size_t)row * NN + j0 + c];
    }
    if (tid == 0) { sh_tot[0] = 0; sh_tot[1] = 0; }
    __syncthreads();

    float v = 0.f, rt = 0.f, tl = 1.f;
    const float DECAY = 0.99004983374916805f;   // fp32(exp(-1/100))

    for (int t = 0; t < TT; ++t) {
        float x0 = 0.f, x1 = 0.f, x2 = 0.f, x3 = 0.f;
        if (wp == 0) {
            const int j = j0 + l;
            x0 = g_Xpart[(size_t)(0 * 320 + t) * NN + j];
            x1 = g_Xpart[(size_t)(1 * 320 + t) * NN + j];
            x2 = g_Xpart[(size_t)(2 * 320 + t) * NN + j];
            x3 = g_Xpart[(size_t)(3 * 320 + t) * NN + j];
            if (t > 0) {
                // poll ONE flag word (lane 0), then burst-read slots directly
                if (l == 0) {
                    while (ldcg32(&g_flag[t - 1]) != (unsigned)t) {}
                }
                __syncwarp();
                const unsigned long long* slot = &g_slot[t - 1][4 * l];
                const unsigned want = (unsigned)t;
                unsigned long long a0, a1, b0, b1;
                bool okA = false, okB = false;
                while (1) {          // tag-checked; first try should succeed
                    if (!okA) {
                        ldcgv2(slot, a0, a1);
                        okA = ((unsigned)(a0 >> 32) == want) & ((unsigned)(a1 >> 32) == want);
                    }
                    if (!okB) {
                        ldcgv2(slot + 2, b0, b1);
                        okB = ((unsigned)(b0 >> 32) == want) & ((unsigned)(b1 >> 32) == want);
                    }
                    if (__all_sync(0xffffffffu, okA & okB)) break;
                }
                // scan: split prefix sums for cached (words<48) / uncached lists
                unsigned m0 = (unsigned)a0, m1 = (unsigned)a1;
                unsigned m2 = (unsigned)b0, m3 = (unsigned)b1;
                unsigned c0 = __popc(m0), c1 = __popc(m1);
                unsigned c2 = __popc(m2), c3 = __popc(m3);
                unsigned s4 = c0 + c1 + c2 + c3;
                unsigned incl = s4;
                #pragma unroll
                for (int d = 1; d < 32; d <<= 1) {
                    unsigned o = __shfl_up_sync(0xffffffffu, incl, d);
                    if (l >= d) incl += o;
                }
                unsigned cTot = __shfl_sync(0xffffffffu, incl, 11);  // words 0..47
                unsigned aTot = __shfl_sync(0xffffffffu, incl, 31);
                if (l == 0) { sh_tot[0] = (int)cTot; sh_tot[1] = (int)(aTot - cTot); }
                unsigned excl = incl - s4;
                int b0o = (l < 12) ? (int)excl : (int)(excl - cTot);
                sh_mask[4 * l]     = m0;  sh_off[4 * l]     = b0o;
                sh_mask[4 * l + 1] = m1;  sh_off[4 * l + 1] = b0o + (int)c0;
                sh_mask[4 * l + 2] = m2;  sh_off[4 * l + 2] = b0o + (int)(c0 + c1);
                sh_mask[4 * l + 3] = m3;  sh_off[4 * l + 3] = b0o + (int)(c0 + c1 + c2);
            }
        }
        __syncthreads();   // S1a: masks + offsets ready

        if (t > 0 && tid < 128) {   // expansion into the two lists
            unsigned bits = sh_mask[tid];
            int o = sh_off[tid];
            int base = tid << 5;
            if (tid < CW) {
                while (bits) { int b = __ffs(bits) - 1; bits &= bits - 1u;
                               idxC[o++] = (unsigned short)(base + b); }
            } else {
                while (bits) { int b = __ffs(bits) - 1; bits &= bits - 1u;
                               idxU[o++] = (unsigned short)(base + b); }
            }
        }
        __syncthreads();   // S1b: index lists ready

        // ---- cached gather: conflict-free scalar LDS (lane = column) ----
        {
            const int SC = sh_tot[0];
            float acc = 0.f, acc2 = 0.f;
            for (int base = wp * 8; base < SC; base += 128) {
                float r[8];
                #pragma unroll
                for (int u = 0; u < 8; ++u) {
                    int kk = base + u;
                    float z = 0.f;
                    if (kk < SC) z = cache[(int)idxC[kk] * CSTR + l];
                    r[u] = z;
                }
                acc  += (r[0] + r[1]) + (r[2] + r[3]);
                acc2 += (r[4] + r[5]) + (r[6] + r[7]);
            }
            part_c[wp][l] = acc + acc2;
        }

        // ---- uncached gather: 4 rows per LDG.128 wave, batch of 8 ----
        {
            const int SU = sh_tot[1];
            const float* wr = w_rec + j0 + (ln8 << 2);
            float4 acc = make_float4(0.f, 0.f, 0.f, 0.f);
            const int myrow = (wp << 2) + sub;
            for (int base = 0; base < SU; base += 512) {
                float4 rv[8];
                #pragma unroll
                for (int u = 0; u < 8; ++u) {
                    int kk = base + (u << 6) + myrow;
                    float4 z = make_float4(0.f, 0.f, 0.f, 0.f);
                    if (kk < SU) z = ldcg128(wr + ((size_t)idxU[kk] << 12));
                    rv[u] = z;
                }
                #pragma unroll
                for (int u = 0; u < 8; ++u) {
                    acc.x += rv[u].x; acc.y += rv[u].y;
                    acc.z += rv[u].z; acc.w += rv[u].w;
                }
            }
            acc.x += __shfl_down_sync(0xffffffffu, acc.x, 16);
            acc.y += __shfl_down_sync(0xffffffffu, acc.y, 16);
            acc.z += __shfl_down_sync(0xffffffffu, acc.z, 16);
            acc.w += __shfl_down_sync(0xffffffffu, acc.w, 16);
            acc.x += __shfl_down_sync(0xffffffffu, acc.x, 8);
            acc.y += __shfl_down_sync(0xffffffffu, acc.y, 8);
            acc.z += __shfl_down_sync(0xffffffffu, acc.z, 8);
            acc.w += __shfl_down_sync(0xffffffffu, acc.w, 8);
            if (l < 8) part4[wp][ln8] = acc;
        }
        __syncthreads();   // S2: partials ready

        if (wp == 0) {
            const float* pf = (const float*)part4;   // row stride 36 floats
            float xr = 0.f;
            #pragma unroll
            for (int w16 = 0; w16 < 16; ++w16) xr += pf[w16 * 36 + l];
            float xc = 0.f;
            #pragma unroll
            for (int w16 = 0; w16 < 16; ++w16) xc += part_c[w16][l];
            float xt = (xr + xc) + ((x0 + x1) + (x2 + x3));
            // LIF dynamics, exact reference order
            v *= DECAY;
            float xin = (rt > 0.f) ? 0.f : xt;
            rt -= 1.f;
            v += xin;
            bool sp = (v >= 10.f);
            if (sp) { tl = (float)t / 300.0f; rt = 1.f; v = 0.f; }

            unsigned ball = __ballot_sync(0xffffffffu, sp);
            if (t < TT - 1 && l == 0)
                stcg64(&g_slot[t][bid],
                       ((unsigned long long)(unsigned)(t + 1) << 32) |
                       (unsigned long long)ball);
            const int j = j0 + l;
            out[(size_t)t * NN + j]            = sp ? 1.f : 0.f;
            out[(size_t)(TT + t) * NN + j]     = tl;
            out[(size_t)(2 * TT + t) * NN + j] = v;
        }
        // WAR safety: list/total writes for t+1 happen after S1a(t+1), which
        // requires warp 0's arrival (post-epilogue); part arrays written before
        // S2(t+1), read by warp 0 only after S2. No extra barriers needed.
    }
}

// ---------------- launch ----------------
extern "C" void kernel_launch(void* const* d_in, const int* in_sizes, int n_in,
                              void* d_out, int out_size) {
    const int* inp; const float* w; const float* w_rec;
    if (in_sizes[0] == TT * NN) {
        inp = (const int*)d_in[0]; w = (const float*)d_in[1]; w_rec = (const float*)d_in[2];
    } else if (n_in > 1 && in_sizes[1] == TT * NN) {
        inp = (const int*)d_in[1]; w = (const float*)d_in[0]; w_rec = (const float*)d_in[2];
    } else {
        inp = (const int*)d_in[2]; w = (const float*)d_in[0]; w_rec = (const float*)d_in[1];
    }
    float* out = (float*)d_out;

    cudaFuncSetAttribute(lif_kernel, cudaFuncAttributeMaxDynamicSharedMemorySize, SMEM_SZ);

    pack_kernel<<<160, 256>>>(inp);
    xgemm_kernel<<<640, NT1>>>(w);
    lif_kernel<<<NBLK + 1, NT2, SMEM_SZ>>>(w_rec, out);
}

// round 13
// speedup vs baseline: 1.3218x; 1.3218x over previous
#include <cuda_runtime.h>

#define NN   4096
#define TT   300
#define TW   10
#define NBLK 128
#define NT1  256
#define NT2  512
#define CW    48                 // cached slot words (rows 0..1535)
#define CROWS (CW * 32)          // 1536
#define CSTR  33                 // cache row stride in floats (conflict-free)

// smem layout offsets (bytes)
#define OFF_CACHE  0
#define OFF_PART4  (CROWS * CSTR * 4)             // 202752 (16B aligned)
#define OFF_PARTC  (OFF_PART4 + 11 * 9 * 16)      // 204336
#define OFF_IDXU   (OFF_PARTC + 4 * 33 * 4)       // 204864
#define OFF_MASK   (OFF_IDXU + 2560 * 2)          // 209984
#define OFF_OFFS   (OFF_MASK + 128 * 4)           // 210496
#define OFF_TOT    (OFF_OFFS + 128 * 4)           // 211008
#define SMEM_SZ    (OFF_TOT + 16)                 // 211024

// ---------------- device scratch ----------------
__device__ unsigned g_mask[NN * TW];
__device__ float    g_Xpart[4ull * 320 * NN];
__device__ __align__(256) unsigned long long g_slot[TT][NBLK];  // producers -> aggregator
__device__ __align__(256) unsigned long long g_rec[TT][NBLK];   // aggregator -> consumers

__device__ __forceinline__ void ldcgv2(const unsigned long long* p,
                                       unsigned long long& a, unsigned long long& b) {
    asm volatile("ld.global.cg.v2.u64 {%0,%1}, [%2];" : "=l"(a), "=l"(b) : "l"(p));
}
__device__ __forceinline__ void stcgv2(unsigned long long* p,
                                       unsigned long long a, unsigned long long b) {
    asm volatile("st.global.cg.v2.u64 [%0], {%1,%2};" :: "l"(p), "l"(a), "l"(b));
}
__device__ __forceinline__ void stcg64(unsigned long long* p, unsigned long long v) {
    asm volatile("st.global.cg.b64 [%0], %1;" :: "l"(p), "l"(v));
}
__device__ __forceinline__ float4 ldcg128(const float* p) {
    float4 v;
    asm volatile("ld.global.cg.v4.f32 {%0,%1,%2,%3}, [%4];"
                 : "=f"(v.x), "=f"(v.y), "=f"(v.z), "=f"(v.w) : "l"(p));
    return v;
}

// ---------------- kernel 1: pack inp bits + clear sync state ----------------
__global__ void __launch_bounds__(256) pack_kernel(const int* __restrict__ inp) {
    const int blk  = blockIdx.x;
    const int word = blk % TW;
    const int i    = (blk / TW) * 256 + threadIdx.x;
    unsigned m = 0u;
    const int tb = word * 32;
    #pragma unroll
    for (int b = 0; b < 32; ++b) {
        int t = tb + b;
        if (t < TT) m |= (((unsigned)inp[(size_t)t * NN + i]) & 1u) << b;
    }
    g_mask[i * TW + word] = m;
    int gid = blk * 256 + threadIdx.x;
    if (gid < TT * NBLK) {
        ((unsigned long long*)g_slot)[gid] = 0ull;
        ((unsigned long long*)g_rec)[gid]  = 0ull;
    }
}

// ---------------- kernel 2: X partials via packed f32x2 FFMA (exact) ----------
__global__ void __launch_bounds__(NT1) xgemm_kernel(const float* __restrict__ w) {
    __shared__ unsigned long long Adup[128][18];
    const int tid  = threadIdx.x;
    const int tile = blockIdx.x;
    int word = tile % 10;
    int ccq  = tile / 10;
    int cc   = ccq >> 2;
    int q    = ccq & 3;
    int j    = cc * 256 + tid;
    int ibase = q * 1024;

    unsigned long long acc[16];
    #pragma unroll
    for (int k = 0; k < 16; ++k) acc[k] = 0ull;

    for (int sub = 0; sub < 8; ++sub) {
        int ib = ibase + sub * 128;
        __syncthreads();
        for (int e = tid; e < 2048; e += NT1) {
            int ii = e >> 4, tp = e & 15;
            unsigned m  = g_mask[(ib + ii) * TW + word];
            unsigned lo = (m >> (2 * tp))     & 1u ? 0x3f800000u : 0u;
            unsigned hi = (m >> (2 * tp + 1)) & 1u ? 0x3f800000u : 0u;
            Adup[ii][tp] = ((unsigned long long)hi << 32) | lo;
        }
        __syncthreads();
        for (int ii = 0; ii < 128; ++ii) {
            unsigned wu = __float_as_uint(w[(size_t)(ib + ii) * NN + j]);
            unsigned long long wpk;
            asm("mov.b64 %0, {%1, %1};" : "=l"(wpk) : "r"(wu));
            const ulonglong2* ap = (const ulonglong2*)(&Adup[ii][0]);
            #pragma unroll
            for (int k = 0; k < 8; ++k) {
                ulonglong2 a2 = ap[k];
                asm("fma.rn.f32x2 %0, %1, %2, %0;" : "+l"(acc[2*k])   : "l"(wpk), "l"(a2.x));
                asm("fma.rn.f32x2 %0, %1, %2, %0;" : "+l"(acc[2*k+1]) : "l"(wpk), "l"(a2.y));
            }
        }
    }
    #pragma unroll
    for (int tp = 0; tp < 16; ++tp) {
        int t0 = word * 32 + 2 * tp;
        g_Xpart[((size_t)q * 320 + t0)     * NN + j] = __uint_as_float((unsigned)acc[tp]);
        g_Xpart[((size_t)q * 320 + t0 + 1) * NN + j] = __uint_as_float((unsigned)(acc[tp] >> 32));
    }
}

// ---------------- kernel 3: persistent recurrent LIF ---------------------------
// Blocks 0..127: workers. Block 128: aggregator (sole poller of g_slot; relays
// tagged masks into g_rec, which workers tag-poll directly — no flag hop).
// Worker roles: warp 0 control; warps 1-4 smem-cached gather (rows 0..1535,
// straight from mask bits, broadcast LDS); warps 5-15 float4 L2 gather.
__global__ void __launch_bounds__(NT2, 1)
lif_kernel(const float* __restrict__ w_rec, float* __restrict__ out) {
    extern __shared__ char sm[];
    float*          cache   = (float*)(sm + OFF_CACHE);            // [1536][33]
    float4        (*part4)[9]  = (float4(*)[9])(sm + OFF_PART4);   // warps 5-15
    float         (*part_c)[33] = (float(*)[33])(sm + OFF_PARTC);  // warps 1-4
    unsigned short* idxU    = (unsigned short*)(sm + OFF_IDXU);    // uncached rows
    unsigned*       sh_mask = (unsigned*)(sm + OFF_MASK);
    int*            sh_off  = (int*)(sm + OFF_OFFS);
    int*            sh_tot  = (int*)(sm + OFF_TOT);                // [1] = SU

    const int tid = threadIdx.x;
    const int bid = blockIdx.x;
    const int l   = tid & 31;
    const int wp  = tid >> 5;

    // ================= aggregator block =================
    if (bid == NBLK) {
        if (wp != 0) return;
        for (int t = 0; t < TT - 1; ++t) {
            const unsigned long long* slot = &g_slot[t][4 * l];
            const unsigned want = (unsigned)(t + 1);
            unsigned long long a0, a1, b0, b1;
            bool okA = false, okB = false;
            while (1) {
                if (!okA) {
                    ldcgv2(slot, a0, a1);
                    okA = ((unsigned)(a0 >> 32) == want) & ((unsigned)(a1 >> 32) == want);
                }
                if (!okB) {
                    ldcgv2(slot + 2, b0, b1);
                    okB = ((unsigned)(b0 >> 32) == want) & ((unsigned)(b1 >> 32) == want);
                }
                if (__all_sync(0xffffffffu, okA & okB)) break;
            }
            // relay tagged masks verbatim; tags make each word self-validating
            stcgv2(&g_rec[t][4 * l], a0, a1);
            stcgv2(&g_rec[t][4 * l + 2], b0, b1);
        }
        return;
    }

    // ================= worker blocks =================
    const int sub = l >> 3;
    const int ln8 = l & 7;
    const int j0  = bid * 32;

    // preload smem weight cache (rows 0..1535, this block's 32 columns)
    for (int q = tid; q < CROWS * 32; q += NT2) {
        int row = q >> 5, c = q & 31;
        cache[row * CSTR + c] = w_rec[(size_t)row * NN + j0 + c];
    }
    if (tid < 128) sh_mask[tid] = 0u;
    if (tid == 0) { sh_tot[0] = 0; sh_tot[1] = 0; }
    __syncthreads();

    float v = 0.f, rt = 0.f, tl = 1.f;
    const float DECAY = 0.99004983374916805f;   // fp32(exp(-1/100))

    for (int t = 0; t < TT; ++t) {
        float x0 = 0.f, x1 = 0.f, x2 = 0.f, x3 = 0.f;
        if (wp == 0) {
            const int j = j0 + l;
            x0 = g_Xpart[(size_t)(0 * 320 + t) * NN + j];
            x1 = g_Xpart[(size_t)(1 * 320 + t) * NN + j];
            x2 = g_Xpart[(size_t)(2 * 320 + t) * NN + j];
            x3 = g_Xpart[(size_t)(3 * 320 + t) * NN + j];
            if (t > 0) {
                // tag-poll the relay record directly (low-rate, spread lines)
                const unsigned long long* rec = &g_rec[t - 1][4 * l];
                const unsigned want = (unsigned)t;
                unsigned long long a0, a1, b0, b1;
                bool okA = false, okB = false;
                while (1) {
                    if (!okA) {
                        ldcgv2(rec, a0, a1);
                        okA = ((unsigned)(a0 >> 32) == want) & ((unsigned)(a1 >> 32) == want);
                    }
                    if (!okB) {
                        ldcgv2(rec + 2, b0, b1);
                        okB = ((unsigned)(b0 >> 32) == want) & ((unsigned)(b1 >> 32) == want);
                    }
                    if (__all_sync(0xffffffffu, okA & okB)) break;
                }
                // scan: inclusive prefix; uncached offsets relative to list start
                unsigned m0 = (unsigned)a0, m1 = (unsigned)a1;
                unsigned m2 = (unsigned)b0, m3 = (unsigned)b1;
                unsigned c0 = __popc(m0), c1 = __popc(m1);
                unsigned c2 = __popc(m2), c3 = __popc(m3);
                unsigned s4 = c0 + c1 + c2 + c3;
                unsigned incl = s4;
                #pragma unroll
                for (int d = 1; d < 32; d <<= 1) {
                    unsigned o = __shfl_up_sync(0xffffffffu, incl, d);
                    if (l >= d) incl += o;
                }
                unsigned cTot = __shfl_sync(0xffffffffu, incl, 11);  // words 0..47
                unsigned aTot = __shfl_sync(0xffffffffu, incl, 31);
                if (l == 0) sh_tot[1] = (int)(aTot - cTot);
                unsigned excl = incl - s4;
                int b0o = (l < 12) ? (int)excl : (int)(excl - cTot);
                sh_mask[4 * l]     = m0;  sh_off[4 * l]     = b0o;
                sh_mask[4 * l + 1] = m1;  sh_off[4 * l + 1] = b0o + (int)c0;
                sh_mask[4 * l + 2] = m2;  sh_off[4 * l + 2] = b0o + (int)(c0 + c1);
                sh_mask[4 * l + 3] = m3;  sh_off[4 * l + 3] = b0o + (int)(c0 + c1 + c2);
            }
        }
        __syncthreads();   // S1a: masks + offsets ready

        if (t > 0 && tid >= CW && tid < 128) {   // expand uncached words only
            unsigned bits = sh_mask[tid];
            int o = sh_off[tid];
            int base = tid << 5;
            while (bits) {
                int b = __ffs(bits) - 1;
                bits &= bits - 1u;
                idxU[o++] = (unsigned short)(base + b);
            }
        }
        __syncthreads();   // S1b: uncached index list ready

        if (wp >= 1 && wp <= 4) {
            // ---- cached gather: broadcast LDS straight from mask bits ----
            float acc = 0.f, acc2 = 0.f;
            if (t > 0) {
                const int w0 = 12 * (wp - 1);
                #pragma unroll
                for (int k = 0; k < 12; ++k) {
                    unsigned m = sh_mask[w0 + k];
                    const float* cb = cache + (((w0 + k) << 5) * CSTR) + l;
                    while (m) {
                        int b1 = __ffs(m) - 1; m &= m - 1u;
                        if (m) {
                            int b2 = __ffs(m) - 1; m &= m - 1u;
                            acc  += cb[b1 * CSTR];
                            acc2 += cb[b2 * CSTR];
                        } else {
                            acc += cb[b1 * CSTR];
                        }
                    }
                }
            }
            part_c[wp - 1][l] = acc + acc2;
        } else if (wp >= 5) {
            // ---- uncached gather: 4 rows per LDG.128 wave, batch of 8 ----
            const int SU = sh_tot[1];
            const float* wr = w_rec + j0 + (ln8 << 2);
            float4 acc = make_float4(0.f, 0.f, 0.f, 0.f);
            const int myrow = ((wp - 5) << 2) + sub;    // 0..43
            for (int base = 0; base < SU; base += 352) {
                float4 rv[8];
                #pragma unroll
                for (int u = 0; u < 8; ++u) {
                    int kk = base + u * 44 + myrow;
                    float4 z = make_float4(0.f, 0.f, 0.f, 0.f);
                    if (kk < SU) z = ldcg128(wr + ((size_t)idxU[kk] << 12));
                    rv[u] = z;
                }
                #pragma unroll
                for (int u = 0; u < 8; ++u) {
                    acc.x += rv[u].x; acc.y += rv[u].y;
                    acc.z += rv[u].z; acc.w += rv[u].w;
                }
            }
            acc.x += __shfl_down_sync(0xffffffffu, acc.x, 16);
            acc.y += __shfl_down_sync(0xffffffffu, acc.y, 16);
            acc.z += __shfl_down_sync(0xffffffffu, acc.z, 16);
            acc.w += __shfl_down_sync(0xffffffffu, acc.w, 16);
            acc.x += __shfl_down_sync(0xffffffffu, acc.x, 8);
            acc.y += __shfl_down_sync(0xffffffffu, acc.y, 8);
            acc.z += __shfl_down_sync(0xffffffffu, acc.z, 8);
            acc.w += __shfl_down_sync(0xffffffffu, acc.w, 8);
            if (l < 8) part4[wp - 5][ln8] = acc;
        }
        __syncthreads();   // S2: partials ready

        if (wp == 0) {
            const float* pf = (const float*)part4;   // row stride 36 floats
            float xr = 0.f;
            #pragma unroll
            for (int w11 = 0; w11 < 11; ++w11) xr += pf[w11 * 36 + l];
            float xc = 0.f;
            #pragma unroll
            for (int w4 = 0; w4 < 4; ++w4) xc += part_c[w4][l];
            float xt = (xr + xc) + ((x0 + x1) + (x2 + x3));
            // LIF dynamics, exact reference order
            v *= DECAY;
            float xin = (rt > 0.f) ? 0.f : xt;
            rt -= 1.f;
            v += xin;
            bool sp = (v >= 10.f);
            if (sp) { tl = (float)t / 300.0f; rt = 1.f; v = 0.f; }

            unsigned ball = __ballot_sync(0xffffffffu, sp);
            if (t < TT - 1 && l == 0)
                stcg64(&g_slot[t][bid],
                       ((unsigned long long)(unsigned)(t + 1) << 32) |
                       (unsigned long long)ball);
            const int j = j0 + l;
            out[(size_t)t * NN + j]            = sp ? 1.f : 0.f;
            out[(size_t)(TT + t) * NN + j]     = tl;
            out[(size_t)(2 * TT + t) * NN + j] = v;
        }
        // WAR safety: sh_mask/idxU for t+1 written after S1a(t+1)/S1b(t+1),
        // which warp 0 joins only post-epilogue; part arrays re-written only
        // before S2(t+1). No extra barriers needed.
    }
}

// ---------------- launch ----------------
extern "C" void kernel_launch(void* const* d_in, const int* in_sizes, int n_in,
                              void* d_out, int out_size) {
    const int* inp; const float* w; const float* w_rec;
    if (in_sizes[0] == TT * NN) {
        inp = (const int*)d_in[0]; w = (const float*)d_in[1]; w_rec = (const float*)d_in[2];
    } else if (n_in > 1 && in_sizes[1] == TT * NN) {
        inp = (const int*)d_in[1]; w = (const float*)d_in[0]; w_rec = (const float*)d_in[2];
    } else {
        inp = (const int*)d_in[2]; w = (const float*)d_in[0]; w_rec = (const float*)d_in[1];
    }
    float* out = (float*)d_out;

    cudaFuncSetAttribute(lif_kernel, cudaFuncAttributeMaxDynamicSharedMemorySize, SMEM_SZ);

    pack_kernel<<<160, 256>>>(inp);
    xgemm_kernel<<<640, NT1>>>(w);
    lif_kernel<<<NBLK + 1, NT2, SMEM_SZ>>>(w_rec, out);
}

// round 14
// speedup vs baseline: 1.5064x; 1.1396x over previous
#include <cuda_runtime.h>

#define NN   4096
#define TT   300
#define TW   10
#define NBLK 128
#define NT1  256
#define NT2  512

// ---------------- device scratch ----------------
__device__ unsigned g_mask[NN * TW];
__device__ float    g_Xpart[4ull * 320 * NN];
__device__ __align__(256) unsigned long long g_slot[TT][NBLK];  // {tag=t+1, mask}
__device__ unsigned g_cnt;                                       // cumulative publishes

__device__ __forceinline__ void ldcgv2(const unsigned long long* p,
                                       unsigned long long& a, unsigned long long& b) {
    asm volatile("ld.global.cg.v2.u64 {%0,%1}, [%2];" : "=l"(a), "=l"(b) : "l"(p));
}
__device__ __forceinline__ void stcg64(unsigned long long* p, unsigned long long v) {
    asm volatile("st.global.cg.b64 [%0], %1;" :: "l"(p), "l"(v));
}
__device__ __forceinline__ unsigned ldcg32(const unsigned* p) {
    unsigned v; asm volatile("ld.global.cg.b32 %0, [%1];" : "=r"(v) : "l"(p)); return v;
}
__device__ __forceinline__ void red_release_add(unsigned* p, unsigned v) {
    asm volatile("red.release.gpu.global.add.u32 [%0], %1;" :: "l"(p), "r"(v) : "memory");
}
__device__ __forceinline__ float4 ldnc128(const float* p) {
    float4 v;
    asm volatile("ld.global.nc.v4.f32 {%0,%1,%2,%3}, [%4];"
                 : "=f"(v.x), "=f"(v.y), "=f"(v.z), "=f"(v.w) : "l"(p));
    return v;
}

// ---------------- kernel 1: pack inp bits + clear sync state ----------------
__global__ void __launch_bounds__(256) pack_kernel(const int* __restrict__ inp) {
    const int blk  = blockIdx.x;
    const int word = blk % TW;
    const int i    = (blk / TW) * 256 + threadIdx.x;
    unsigned m = 0u;
    const int tb = word * 32;
    #pragma unroll
    for (int b = 0; b < 32; ++b) {
        int t = tb + b;
        if (t < TT) m |= (((unsigned)inp[(size_t)t * NN + i]) & 1u) << b;
    }
    g_mask[i * TW + word] = m;
    int gid = blk * 256 + threadIdx.x;
    if (gid < TT * NBLK) ((unsigned long long*)g_slot)[gid] = 0ull;
    if (gid == 0) g_cnt = 0u;
}

// ---------------- kernel 2: X partials via packed f32x2 FFMA (exact) ----------
__global__ void __launch_bounds__(NT1) xgemm_kernel(const float* __restrict__ w) {
    __shared__ unsigned long long Adup[128][18];
    const int tid  = threadIdx.x;
    const int tile = blockIdx.x;
    int word = tile % 10;
    int ccq  = tile / 10;
    int cc   = ccq >> 2;
    int q    = ccq & 3;
    int j    = cc * 256 + tid;
    int ibase = q * 1024;

    unsigned long long acc[16];
    #pragma unroll
    for (int k = 0; k < 16; ++k) acc[k] = 0ull;

    for (int sub = 0; sub < 8; ++sub) {
        int ib = ibase + sub * 128;
        __syncthreads();
        for (int e = tid; e < 2048; e += NT1) {
            int ii = e >> 4, tp = e & 15;
            unsigned m  = g_mask[(ib + ii) * TW + word];
            unsigned lo = (m >> (2 * tp))     & 1u ? 0x3f800000u : 0u;
            unsigned hi = (m >> (2 * tp + 1)) & 1u ? 0x3f800000u : 0u;
            Adup[ii][tp] = ((unsigned long long)hi << 32) | lo;
        }
        __syncthreads();
        for (int ii = 0; ii < 128; ++ii) {
            unsigned wu = __float_as_uint(w[(size_t)(ib + ii) * NN + j]);
            unsigned long long wpk;
            asm("mov.b64 %0, {%1, %1};" : "=l"(wpk) : "r"(wu));
            const ulonglong2* ap = (const ulonglong2*)(&Adup[ii][0]);
            #pragma unroll
            for (int k = 0; k < 8; ++k) {
                ulonglong2 a2 = ap[k];
                asm("fma.rn.f32x2 %0, %1, %2, %0;" : "+l"(acc[2*k])   : "l"(wpk), "l"(a2.x));
                asm("fma.rn.f32x2 %0, %1, %2, %0;" : "+l"(acc[2*k+1]) : "l"(wpk), "l"(a2.y));
            }
        }
    }
    #pragma unroll
    for (int tp = 0; tp < 16; ++tp) {
        int t0 = word * 32 + 2 * tp;
        g_Xpart[((size_t)q * 320 + t0)     * NN + j] = __uint_as_float((unsigned)acc[tp]);
        g_Xpart[((size_t)q * 320 + t0 + 1) * NN + j] = __uint_as_float((unsigned)(acc[tp] >> 32));
    }
}

// ---------------- kernel 3: persistent recurrent LIF (R11 + counter sync) ----
// Producers: st.cg slot, then red.release.add on ONE counter.
// Consumers: 1 lane polls the counter (cnt >= 128*t), then burst-reads slots.
__global__ void __launch_bounds__(NT2, 1)
lif_kernel(const float* __restrict__ w_rec, float* __restrict__ out) {
    __shared__ unsigned sh_mask[128];
    __shared__ int      sh_off[128];
    __shared__ int      sh_total;
    __shared__ int      sh_idx[NN];
    __shared__ float4   part4[16][9];

    const int tid = threadIdx.x;
    const int bid = blockIdx.x;
    const int l   = tid & 31;
    const int wp  = tid >> 5;
    const int sub = l >> 3;
    const int ln8 = l & 7;
    const int j0  = bid * 32;

    if (tid == 0) sh_total = 0;

    float v = 0.f, rt = 0.f, tl = 1.f;
    const float DECAY = 0.99004983374916805f;   // fp32(exp(-1/100))

    for (int t = 0; t < TT; ++t) {
        float x0 = 0.f, x1 = 0.f, x2 = 0.f, x3 = 0.f;
        if (wp == 0) {
            const int j = j0 + l;
            x0 = g_Xpart[(size_t)(0 * 320 + t) * NN + j];
            x1 = g_Xpart[(size_t)(1 * 320 + t) * NN + j];
            x2 = g_Xpart[(size_t)(2 * 320 + t) * NN + j];
            x3 = g_Xpart[(size_t)(3 * 320 + t) * NN + j];
            if (t > 0) {
                // poll ONE counter word (lane 0 only, tight spin)
                if (l == 0) {
                    const unsigned want = 128u * (unsigned)t;
                    while (ldcg32(&g_cnt) < want) {}
                }
                __syncwarp();
                // burst-read slots, tag-checked (first try succeeds)
                const unsigned long long* slot = &g_slot[t - 1][4 * l];
                const unsigned want = (unsigned)t;
                unsigned long long a0, a1, b0, b1;
                bool okA = false, okB = false;
                while (1) {
                    if (!okA) {
                        ldcgv2(slot, a0, a1);
                        okA = ((unsigned)(a0 >> 32) == want) & ((unsigned)(a1 >> 32) == want);
                    }
                    if (!okB) {
                        ldcgv2(slot + 2, b0, b1);
                        okB = ((unsigned)(b0 >> 32) == want) & ((unsigned)(b1 >> 32) == want);
                    }
                    if (__all_sync(0xffffffffu, okA & okB)) break;
                }
                // scan in registers -> per-word offsets
                unsigned m0 = (unsigned)a0, m1 = (unsigned)a1;
                unsigned m2 = (unsigned)b0, m3 = (unsigned)b1;
                unsigned c0 = __popc(m0), c1 = __popc(m1);
                unsigned c2 = __popc(m2), c3 = __popc(m3);
                unsigned s4 = c0 + c1 + c2 + c3;
                unsigned incl = s4;
                #pragma unroll
                for (int d = 1; d < 32; d <<= 1) {
                    unsigned o = __shfl_up_sync(0xffffffffu, incl, d);
                    if (l >= d) incl += o;
                }
                if (l == 31) sh_total = (int)incl;
                unsigned excl = incl - s4;
                sh_mask[4 * l]     = m0;  sh_off[4 * l]     = (int)excl;
                sh_mask[4 * l + 1] = m1;  sh_off[4 * l + 1] = (int)(excl + c0);
                sh_mask[4 * l + 2] = m2;  sh_off[4 * l + 2] = (int)(excl + c0 + c1);
                sh_mask[4 * l + 3] = m3;  sh_off[4 * l + 3] = (int)(excl + c0 + c1 + c2);
            }
        }
        __syncthreads();   // S1a: masks + offsets ready

        if (t > 0 && tid < 128) {
            unsigned bits = sh_mask[tid];
            int o = sh_off[tid];
            int base = tid << 5;
            while (bits) {
                int b = __ffs(bits) - 1;
                bits &= bits - 1u;
                sh_idx[o++] = (base + b) << 12;    // row * NN
            }
        }
        __syncthreads();   // S1b: index list ready

        // gather: 4 rows per LDG.128 wave, batch of 8 waves in flight (L1 on)
        {
            const int S = sh_total;
            const float* wr = w_rec + j0 + (ln8 << 2);
            float4 acc = make_float4(0.f, 0.f, 0.f, 0.f);
            const int myrow = (wp << 2) + sub;
            for (int base = 0; base < S; base += 512) {
                float4 rv[8];
                #pragma unroll
                for (int u = 0; u < 8; ++u) {
                    int kk = base + (u << 6) + myrow;
                    float4 z = make_float4(0.f, 0.f, 0.f, 0.f);
                    if (kk < S) z = ldnc128(wr + sh_idx[kk]);
                    rv[u] = z;
                }
                #pragma unroll
                for (int u = 0; u < 8; ++u) {
                    acc.x += rv[u].x; acc.y += rv[u].y;
                    acc.z += rv[u].z; acc.w += rv[u].w;
                }
            }
            acc.x += __shfl_down_sync(0xffffffffu, acc.x, 16);
            acc.y += __shfl_down_sync(0xffffffffu, acc.y, 16);
            acc.z += __shfl_down_sync(0xffffffffu, acc.z, 16);
            acc.w += __shfl_down_sync(0xffffffffu, acc.w, 16);
            acc.x += __shfl_down_sync(0xffffffffu, acc.x, 8);
            acc.y += __shfl_down_sync(0xffffffffu, acc.y, 8);
            acc.z += __shfl_down_sync(0xffffffffu, acc.z, 8);
            acc.w += __shfl_down_sync(0xffffffffu, acc.w, 8);
            if (l < 8) part4[wp][ln8] = acc;
        }
        __syncthreads();   // S2: partials ready

        if (wp == 0) {
            const float* pf = (const float*)part4;   // row stride 36 floats
            float xr = 0.f;
            #pragma unroll
            for (int w16 = 0; w16 < 16; ++w16) xr += pf[w16 * 36 + l];
            float xt = xr + ((x0 + x1) + (x2 + x3));
            // LIF dynamics, exact reference order
            v *= DECAY;
            float xin = (rt > 0.f) ? 0.f : xt;
            rt -= 1.f;
            v += xin;
            bool sp = (v >= 10.f);
            if (sp) { tl = (float)t / 300.0f; rt = 1.f; v = 0.f; }

            // publish FIRST: slot store, then release-increment the counter
            unsigned ball = __ballot_sync(0xffffffffu, sp);
            if (t < TT - 1 && l == 0) {
                stcg64(&g_slot[t][bid],
                       ((unsigned long long)(unsigned)(t + 1) << 32) |
                       (unsigned long long)ball);
                red_release_add(&g_cnt, 1u);
            }
            const int j = j0 + l;
            out[(size_t)t * NN + j]            = sp ? 1.f : 0.f;
            out[(size_t)(TT + t) * NN + j]     = tl;
            out[(size_t)(2 * TT + t) * NN + j] = v;
        }
        // WAR safety: sh_mask/sh_idx(t+1) written after S1a/S1b(t+1), which warp 0
        // joins post-epilogue; part4 rewritten only before S2(t+1).
    }
}

// ---------------- launch ----------------
extern "C" void kernel_launch(void* const* d_in, const int* in_sizes, int n_in,
                              void* d_out, int out_size) {
    const int* inp; const float* w; const float* w_rec;
    if (in_sizes[0] == TT * NN) {
        inp = (const int*)d_in[0]; w = (const float*)d_in[1]; w_rec = (const float*)d_in[2];
    } else if (n_in > 1 && in_sizes[1] == TT * NN) {
        inp = (const int*)d_in[1]; w = (const float*)d_in[0]; w_rec = (const float*)d_in[2];
    } else {
        inp = (const int*)d_in[2]; w = (const float*)d_in[0]; w_rec = (const float*)d_in[1];
    }
    float* out = (float*)d_out;

    pack_kernel<<<160, 256>>>(inp);
    xgemm_kernel<<<640, NT1>>>(w);
    lif_kernel<<<NBLK, NT2>>>(w_rec, out);
}

// round 15
// speedup vs baseline: 1.9014x; 1.2622x over previous
#include <cuda_runtime.h>

#define NN   4096
#define TT   300
#define TW   10
#define NBLK 128
#define NT2  512

// ---------------- device scratch ----------------
__device__ unsigned g_mask[NN * TW];
__device__ float    g_Xpart[4ull * 320 * NN];
__device__ __align__(256) unsigned long long g_slot[TT][NBLK];  // {tag=t+1, mask}
__device__ unsigned g_cnt;                                       // cumulative publishes
__device__ unsigned g_wcnt[TW];                                  // per-word tile counters

__device__ __forceinline__ void ldcgv2(const unsigned long long* p,
                                       unsigned long long& a, unsigned long long& b) {
    asm volatile("ld.global.cg.v2.u64 {%0,%1}, [%2];" : "=l"(a), "=l"(b) : "l"(p));
}
__device__ __forceinline__ void stcg64(unsigned long long* p, unsigned long long v) {
    asm volatile("st.global.cg.b64 [%0], %1;" :: "l"(p), "l"(v));
}
__device__ __forceinline__ unsigned ldcg32(const unsigned* p) {
    unsigned v; asm volatile("ld.global.cg.b32 %0, [%1];" : "=r"(v) : "l"(p)); return v;
}
__device__ __forceinline__ unsigned ldacq32(const unsigned* p) {
    unsigned v; asm volatile("ld.acquire.gpu.global.u32 %0, [%1];" : "=r"(v) : "l"(p)); return v;
}
__device__ __forceinline__ void red_release_add(unsigned* p, unsigned v) {
    asm volatile("red.release.gpu.global.add.u32 [%0], %1;" :: "l"(p), "r"(v) : "memory");
}
__device__ __forceinline__ float4 ldnc128(const float* p) {
    float4 v;
    asm volatile("ld.global.nc.v4.f32 {%0,%1,%2,%3}, [%4];"
                 : "=f"(v.x), "=f"(v.y), "=f"(v.z), "=f"(v.w) : "l"(p));
    return v;
}

#define BAR_LIF()  asm volatile("bar.sync 1, 256;" ::: "memory")
#define BAR_GEMM() asm volatile("bar.sync 2, 256;" ::: "memory")

// ---------------- kernel 1: pack inp bits + clear sync state ----------------
__global__ void __launch_bounds__(256) pack_kernel(const int* __restrict__ inp) {
    const int blk  = blockIdx.x;
    const int word = blk % TW;
    const int i    = (blk / TW) * 256 + threadIdx.x;
    unsigned m = 0u;
    const int tb = word * 32;
    #pragma unroll
    for (int b = 0; b < 32; ++b) {
        int t = tb + b;
        if (t < TT) m |= (((unsigned)inp[(size_t)t * NN + i]) & 1u) << b;
    }
    g_mask[i * TW + word] = m;
    int gid = blk * 256 + threadIdx.x;
    if (gid < TT * NBLK) ((unsigned long long*)g_slot)[gid] = 0ull;
    if (gid == 0) g_cnt = 0u;
    if (gid < TW) g_wcnt[gid] = 0u;
}

// ---------------- kernel 2: fused persistent LIF + background X-GEMM ----------
// 128 blocks x 512 threads. Warps 0-7: R14 LIF pipeline (named barrier 1).
// Warps 8-15: X-GEMM tiles in word-ascending order (named barrier 2), publishing
// per-word completion counters that warp 0 acquire-polls at word boundaries.
__global__ void __launch_bounds__(NT2, 1)
lif_kernel(const float* __restrict__ w, const float* __restrict__ w_rec,
           float* __restrict__ out) {
    __shared__ unsigned long long Adup[128][18];   // xgemm warps only
    __shared__ unsigned sh_mask[128];
    __shared__ int      sh_off[128];
    __shared__ int      sh_total;
    __shared__ int      sh_idx[NN];
    __shared__ float4   part4[8][9];

    const int tid = threadIdx.x;
    const int bid = blockIdx.x;
    const int l   = tid & 31;
    const int wp  = tid >> 5;

    // ================= warps 8-15: background X-GEMM =================
    if (wp >= 8) {
        const int tid2 = tid - 256;
        for (int r = 0; r < 5; ++r) {
            const int tile = bid + (r << 7);       // word-ascending: word = tile>>6
            const int word = tile >> 6;
            const int s    = tile & 63;
            const int cc   = s >> 2;
            const int q    = s & 3;
            const int j    = cc * 256 + tid2;
            const int ibase = q * 1024;

            unsigned long long acc[16];
            #pragma unroll
            for (int k = 0; k < 16; ++k) acc[k] = 0ull;

            for (int sub = 0; sub < 8; ++sub) {
                int ib = ibase + sub * 128;
                BAR_GEMM();
                for (int e = tid2; e < 2048; e += 256) {
                    int ii = e >> 4, tp = e & 15;
                    unsigned m  = g_mask[(ib + ii) * TW + word];
                    unsigned lo = (m >> (2 * tp))     & 1u ? 0x3f800000u : 0u;
                    unsigned hi = (m >> (2 * tp + 1)) & 1u ? 0x3f800000u : 0u;
                    Adup[ii][tp] = ((unsigned long long)hi << 32) | lo;
                }
                BAR_GEMM();
                for (int ii = 0; ii < 128; ++ii) {
                    unsigned wu = __float_as_uint(w[(size_t)(ib + ii) * NN + j]);
                    unsigned long long wpk;
                    asm("mov.b64 %0, {%1, %1};" : "=l"(wpk) : "r"(wu));
                    const ulonglong2* ap = (const ulonglong2*)(&Adup[ii][0]);
                    #pragma unroll
                    for (int k = 0; k < 8; ++k) {
                        ulonglong2 a2 = ap[k];
                        asm("fma.rn.f32x2 %0, %1, %2, %0;" : "+l"(acc[2*k])   : "l"(wpk), "l"(a2.x));
                        asm("fma.rn.f32x2 %0, %1, %2, %0;" : "+l"(acc[2*k+1]) : "l"(wpk), "l"(a2.y));
                    }
                }
            }
            #pragma unroll
            for (int tp = 0; tp < 16; ++tp) {
                int t0 = word * 32 + 2 * tp;
                g_Xpart[((size_t)q * 320 + t0)     * NN + j] = __uint_as_float((unsigned)acc[tp]);
                g_Xpart[((size_t)q * 320 + t0 + 1) * NN + j] = __uint_as_float((unsigned)(acc[tp] >> 32));
            }
            __threadfence();     // make this thread's Xpart stores GPU-visible
            BAR_GEMM();          // all 256 xgemm threads fenced
            if (tid2 == 0) red_release_add(&g_wcnt[word], 1u);   // 64 tiles per word
        }
        return;   // xgemm warps exit; they never touch barrier 1
    }

    // ================= warps 0-7: LIF pipeline (R14, 8 gather warps) ==========
    const int sub = l >> 3;
    const int ln8 = l & 7;
    const int j0  = bid * 32;

    if (tid == 0) sh_total = 0;

    float v = 0.f, rt = 0.f, tl = 1.f;
    const float DECAY = 0.99004983374916805f;   // fp32(exp(-1/100))

    for (int t = 0; t < TT; ++t) {
        float x0 = 0.f, x1 = 0.f, x2 = 0.f, x3 = 0.f;
        if (wp == 0) {
            // wait for this word's Xpart tiles (10 polls total per block)
            if ((t & 31) == 0) {
                if (l == 0) {
                    while (ldacq32(&g_wcnt[t >> 5]) < 64u) {}
                }
                __syncwarp();
            }
            const int j = j0 + l;
            x0 = g_Xpart[(size_t)(0 * 320 + t) * NN + j];
            x1 = g_Xpart[(size_t)(1 * 320 + t) * NN + j];
            x2 = g_Xpart[(size_t)(2 * 320 + t) * NN + j];
            x3 = g_Xpart[(size_t)(3 * 320 + t) * NN + j];
            if (t > 0) {
                // poll ONE counter word (lane 0 only, tight spin)
                if (l == 0) {
                    const unsigned want = 128u * (unsigned)t;
                    while (ldcg32(&g_cnt) < want) {}
                }
                __syncwarp();
                // burst-read slots, tag-checked (first try succeeds)
                const unsigned long long* slot = &g_slot[t - 1][4 * l];
                const unsigned want = (unsigned)t;
                unsigned long long a0, a1, b0, b1;
                bool okA = false, okB = false;
                while (1) {
                    if (!okA) {
                        ldcgv2(slot, a0, a1);
                        okA = ((unsigned)(a0 >> 32) == want) & ((unsigned)(a1 >> 32) == want);
                    }
                    if (!okB) {
                        ldcgv2(slot + 2, b0, b1);
                        okB = ((unsigned)(b0 >> 32) == want) & ((unsigned)(b1 >> 32) == want);
                    }
                    if (__all_sync(0xffffffffu, okA & okB)) break;
                }
                // scan in registers -> per-word offsets
                unsigned m0 = (unsigned)a0, m1 = (unsigned)a1;
                unsigned m2 = (unsigned)b0, m3 = (unsigned)b1;
                unsigned c0 = __popc(m0), c1 = __popc(m1);
                unsigned c2 = __popc(m2), c3 = __popc(m3);
                unsigned s4 = c0 + c1 + c2 + c3;
                unsigned incl = s4;
                #pragma unroll
                for (int d = 1; d < 32; d <<= 1) {
                    unsigned o = __shfl_up_sync(0xffffffffu, incl, d);
                    if (l >= d) incl += o;
                }
                if (l == 31) sh_total = (int)incl;
                unsigned excl = incl - s4;
                sh_mask[4 * l]     = m0;  sh_off[4 * l]     = (int)excl;
                sh_mask[4 * l + 1] = m1;  sh_off[4 * l + 1] = (int)(excl + c0);
                sh_mask[4 * l + 2] = m2;  sh_off[4 * l + 2] = (int)(excl + c0 + c1);
                sh_mask[4 * l + 3] = m3;  sh_off[4 * l + 3] = (int)(excl + c0 + c1 + c2);
            }
        }
        BAR_LIF();   // S1a: masks + offsets ready

        if (t > 0 && tid < 128) {
            unsigned bits = sh_mask[tid];
            int o = sh_off[tid];
            int base = tid << 5;
            while (bits) {
                int b = __ffs(bits) - 1;
                bits &= bits - 1u;
                sh_idx[o++] = (base + b) << 12;    // row * NN
            }
        }
        BAR_LIF();   // S1b: index list ready

        // gather: 8 warps, 4 rows per LDG.128 wave, batch of 8 waves in flight
        {
            const int S = sh_total;
            const float* wr = w_rec + j0 + (ln8 << 2);
            float4 acc = make_float4(0.f, 0.f, 0.f, 0.f);
            const int myrow = (wp << 2) + sub;     // 0..31
            for (int base = 0; base < S; base += 256) {
                float4 rv[8];
                #pragma unroll
                for (int u = 0; u < 8; ++u) {
                    int kk = base + (u << 5) + myrow;
                    float4 z = make_float4(0.f, 0.f, 0.f, 0.f);
                    if (kk < S) z = ldnc128(wr + sh_idx[kk]);
                    rv[u] = z;
                }
                #pragma unroll
                for (int u = 0; u < 8; ++u) {
                    acc.x += rv[u].x; acc.y += rv[u].y;
                    acc.z += rv[u].z; acc.w += rv[u].w;
                }
            }
            acc.x += __shfl_down_sync(0xffffffffu, acc.x, 16);
            acc.y += __shfl_down_sync(0xffffffffu, acc.y, 16);
            acc.z += __shfl_down_sync(0xffffffffu, acc.z, 16);
            acc.w += __shfl_down_sync(0xffffffffu, acc.w, 16);
            acc.x += __shfl_down_sync(0xffffffffu, acc.x, 8);
            acc.y += __shfl_down_sync(0xffffffffu, acc.y, 8);
            acc.z += __shfl_down_sync(0xffffffffu, acc.z, 8);
            acc.w += __shfl_down_sync(0xffffffffu, acc.w, 8);
            if (l < 8) part4[wp][ln8] = acc;
        }
        BAR_LIF();   // S2: partials ready

        if (wp == 0) {
            const float* pf = (const float*)part4;   // row stride 36 floats
            float xr = 0.f;
            #pragma unroll
            for (int w8 = 0; w8 < 8; ++w8) xr += pf[w8 * 36 + l];
            float xt = xr + ((x0 + x1) + (x2 + x3));
            // LIF dynamics, exact reference order
            v *= DECAY;
            float xin = (rt > 0.f) ? 0.f : xt;
            rt -= 1.f;
            v += xin;
            bool sp = (v >= 10.f);
            if (sp) { tl = (float)t / 300.0f; rt = 1.f; v = 0.f; }

            // publish FIRST: slot store, then release-increment the counter
            unsigned ball = __ballot_sync(0xffffffffu, sp);
            if (t < TT - 1 && l == 0) {
                stcg64(&g_slot[t][bid],
                       ((unsigned long long)(unsigned)(t + 1) << 32) |
                       (unsigned long long)ball);
                red_release_add(&g_cnt, 1u);
            }
            const int j = j0 + l;
            out[(size_t)t * NN + j]            = sp ? 1.f : 0.f;
            out[(size_t)(TT + t) * NN + j]     = tl;
            out[(size_t)(2 * TT + t) * NN + j] = v;
        }
        // WAR safety (unchanged from R14): sh_mask/sh_idx(t+1) written after
        // S1a/S1b(t+1), which warp 0 joins post-epilogue; part4 rewritten only
        // before S2(t+1). xgemm warps never touch these arrays or barrier 1.
    }
}

// ---------------- launch ----------------
extern "C" void kernel_launch(void* const* d_in, const int* in_sizes, int n_in,
                              void* d_out, int out_size) {
    const int* inp; const float* w; const float* w_rec;
    if (in_sizes[0] == TT * NN) {
        inp = (const int*)d_in[0]; w = (const float*)d_in[1]; w_rec = (const float*)d_in[2];
    } else if (n_in > 1 && in_sizes[1] == TT * NN) {
        inp = (const int*)d_in[1]; w = (const float*)d_in[0]; w_rec = (const float*)d_in[2];
    } else {
        inp = (const int*)d_in[2]; w = (const float*)d_in[0]; w_rec = (const float*)d_in[1];
    }
    float* out = (float*)d_out;

    pack_kernel<<<160, 256>>>(inp);
    lif_kernel<<<NBLK, NT2>>>(w, w_rec, out);
}